// round 13
// baseline (speedup 1.0000x reference)
#include <cuda_runtime.h>

#define GRIDN 192
#define VOLN (GRIDN*GRIDN*GRIDN)
#define BMW (GRIDN*GRIDN*6)
#define NBINS 80
#define NSUB 16
#define SUBCAP 512
#define NSB (NBINS*NSUB)              // 1280 sub-bins
#define PAIR_CAP (NSB*SUBCAP)
#define MAXN 200000
#define MAXNB 16
#define DUMPROW (MAXN*MAXNB)          // garbage row for overflow pairs
#define TILE 128
#define FSTR 81   // padded smem feature stride (odd -> conflict-free)

// ---------------- persistent device scratch ----------------
// g_vol needs NO per-launch clear: only read at cells whose g_bm bit is set,
// and bits are only set at cells k_scatter wrote in THIS launch.
__device__ int            g_vol[VOLN];
__device__ unsigned       g_bm[BMW];
__device__ float          g_W[NBINS*2304];             // factorized per-bin weights
__device__ float          g_V[NBINS*4];                // vv = sqrt(3)*unit(offset)
__device__ int            g_rowmask[25];
__device__ int            g_rowstart[25];
__device__ int            g_bdx[NBINS], g_bdy[NBINS], g_bdz[NBINS];
__device__ int            g_cursor[NSB];               // despread counters
__device__ int            g_pairnb[PAIR_CAP];          // source point index per pair
__device__ int            g_pairdst[PAIR_CAP];         // dest row (i*MAXNB+r) per pair
__device__ unsigned char  g_pcnt[MAXN];
__device__ float          g_partial[((size_t)MAXN*MAXNB + TILE)*80];  // ~1.02 GB, per-dest rows

// ---------------- clear + geometry init fused (offsets with 1 <= d^2 <= 6) ----------
__global__ void k_clear()
{
    int i = blockIdx.x*blockDim.x + threadIdx.x;
    if (i < BMW)  g_bm[i] = 0u;
    if (i < NSB)  g_cursor[i] = 0;
    if (blockIdx.x == 0 && threadIdx.x == 0) {
        int bin = 0;
        for (int dx = -2; dx <= 2; dx++)
        for (int dy = -2; dy <= 2; dy++) {
            int row = (dx+2)*5 + (dy+2);
            int mask = 0;
            g_rowstart[row] = bin;
            for (int dz = -2; dz <= 2; dz++) {
                int d2 = dx*dx + dy*dy + dz*dz;
                if (d2 >= 1 && d2 <= 6) {
                    mask |= 1 << (dz+2);
                    g_bdx[bin] = dx; g_bdy[bin] = dy; g_bdz[bin] = dz;
                    float inv = 1.7320508075688772f / sqrtf((float)d2);
                    g_V[bin*4+0] = dx*inv; g_V[bin*4+1] = dy*inv; g_V[bin*4+2] = dz*inv;
                    bin++;
                }
            }
            g_rowmask[row] = mask;
        }
    }
}

__global__ void k_scatter(const int* __restrict__ coords, int n)
{
    int i = blockIdx.x*blockDim.x + threadIdx.x;
    if (i >= n) return;
    int x = coords[3*i+0], y = coords[3*i+1], z = coords[3*i+2];
    g_vol[(x*GRIDN + y)*GRIDN + z] = i;
    atomicOr(&g_bm[(x*GRIDN + y)*6 + (z >> 5)], 1u << (z & 31));
}

// ---------------- factorized per-bin weights: g_W[b] = scale * (EMB[b] @ weight)/125 ----
__global__ void __launch_bounds__(256) k_buildW(const float* __restrict__ weight)
{
    int b = blockIdx.x, tid = threadIdx.x;
    int dx = g_bdx[b], dy = g_bdy[b], dz = g_bdz[b];
    float d = sqrtf((float)(dx*dx + dy*dy + dz*dz));
    float e[8];
    const float h = 2.5f / 9.0f;
    const float C = 1.14136f * expf(2.0f);
    #pragma unroll
    for (int r = 0; r < 8; r++) {
        float t  = (d - h*(float)(r+1)) / h;
        float tt = t*t;
        e[r] = (tt < 1.0f) ? C * expf(-2.0f / (1.0f - tt)) : 0.0f;
    }
    const float A  = 0.14433756729740643f;   // 1/sqrt(48)
    const float A3 = 1.0f / 12.0f;           // A/sqrt(3)
    for (int j = tid; j < 2304; j += 256) {
        float w = 0.0f;
        #pragma unroll
        for (int r = 0; r < 8; r++) w += e[r] * __ldg(weight + r*2304 + j);
        float s = (j >= 1792) ? A3 : A;
        g_W[b*2304 + j] = s * w * (1.0f / 125.0f);
    }
}

// ---------------- occupancy probe: 5 z-bits around z for column (xx,yy) ----------------
__device__ __forceinline__ unsigned occ5(int xx, int yy, int z)
{
    int base = (xx*GRIDN + yy)*6;
    int zl = z - 2;
    int q  = zl >> 5;
    unsigned w0 = (q >= 0)   ? g_bm[base + q]     : 0u;
    unsigned w1 = (q + 1 < 6)? g_bm[base + q + 1] : 0u;
    unsigned v = __funnelshift_r(w0, w1, zl & 31) & 31u;
    if (zl + 4 > GRIDN - 1) v &= (31u >> (zl + 4 - (GRIDN - 1)));
    return v;
}

// discovery: phase 1 batches all 21 row probes (max MLP); phase 2 claims
// despread slots and records (source, dest) per pair; r = fixed traversal order
__global__ void k_fill(const int* __restrict__ coords, int n)
{
    int i = blockIdx.x*blockDim.x + threadIdx.x;
    if (i >= n) return;
    int x = __ldg(coords+3*i+0), y = __ldg(coords+3*i+1), z = __ldg(coords+3*i+2);
    int sub = i & (NSUB-1);

    unsigned am[25];
    #pragma unroll
    for (int row = 0; row < 25; row++) {
        int mask = g_rowmask[row];
        am[row] = 0u;
        if (!mask) continue;
        int dx = row/5 - 2, dy = row%5 - 2;
        int xx = x + dx, yy = y + dy;
        if (xx < 0 || xx >= GRIDN || yy < 0 || yy >= GRIDN) continue;
        am[row] = occ5(xx, yy, z) & (unsigned)mask;
    }

    int r = 0;
    #pragma unroll
    for (int row = 0; row < 25; row++) {
        unsigned a = am[row];
        if (!a) continue;
        int mask = g_rowmask[row];
        int dx = row/5 - 2, dy = row%5 - 2;
        int xx = x + dx, yy = y + dy;
        int rs = g_rowstart[row];
        while (a) {
            int bpos = __ffs(a) - 1; a &= a - 1;
            int bin = rs + __popc((unsigned)mask & ((1u << bpos) - 1u));
            int loc = atomicAdd(&g_cursor[bin*NSUB + sub], 1);
            if (loc < SUBCAP) {
                int slot = (bin*NSUB + sub)*SUBCAP + loc;
                int zz = z - 2 + bpos;
                g_pairnb[slot]  = g_vol[(xx*GRIDN + yy)*GRIDN + zz];
                if (r < MAXNB) { g_pairdst[slot] = i*MAXNB + r; r++; }
                else           { g_pairdst[slot] = DUMPROW; }
            }
        }
    }
    g_pcnt[i] = (unsigned char)r;
}

// ---------------- factorized binned GEMM over 1280 sub-bins ----------
// sub-bin sb: weights = g_W[sb>>4], pairs at [sb*SUBCAP, sb*SUBCAP+cnt)
// partial row written directly to per-destination address (scattered store,
// latency-hidden) so k_final reads contiguously.
__global__ void __launch_bounds__(128) k_gemm(const float* __restrict__ feats)
{
    __shared__ float sF[TILE*FSTR];
    __shared__ float sW[2304];
    __shared__ float sVV[4];
    __shared__ int   sPair[TILE];
    __shared__ int   sDst[TILE];
    __shared__ int   sCnt[NSB];
    __shared__ int   sTS[NSB+1];
    __shared__ int   sPart[129];
    int tid = threadIdx.x;

    #pragma unroll
    for (int q = 0; q < 10; q++) {
        int sb = tid*10 + q;
        sCnt[sb] = min(g_cursor[sb], SUBCAP);
    }
    __syncthreads();
    // two-level tile-count prefix scan
    {
        int loc = 0;
        #pragma unroll
        for (int q = 0; q < 10; q++) loc += (sCnt[tid*10 + q] + TILE - 1) / TILE;
        sPart[tid] = loc;
        __syncthreads();
        if (tid == 0) {
            int acc = 0;
            for (int j = 0; j < 128; j++) { int v = sPart[j]; sPart[j] = acc; acc += v; }
            sPart[128] = acc;
        }
        __syncthreads();
        int acc = sPart[tid];
        #pragma unroll
        for (int q = 0; q < 10; q++) {
            sTS[tid*10 + q] = acc;
            acc += (sCnt[tid*10 + q] + TILE - 1) / TILE;
        }
        if (tid == 0) sTS[NSB] = sPart[128];
        __syncthreads();
    }
    int ntiles = sTS[NSB];

    for (int t = blockIdx.x; t < ntiles; t += gridDim.x) {
        int lo = 0, hi = NSB;
        while (hi - lo > 1) { int mid = (lo + hi) >> 1; if (sTS[mid] <= t) lo = mid; else hi = mid; }
        int sb = lo;
        int b  = sb >> 4;
        int tloc  = t - sTS[sb];
        int pbase = sb*SUBCAP + tloc*TILE;
        int m = min(TILE, sCnt[sb] - tloc*TILE);

        if (tid < m) {
            sPair[tid] = g_pairnb[pbase + tid];
            sDst[tid]  = g_pairdst[pbase + tid];
        }
        #pragma unroll
        for (int q = 0; q < 18; q++) sW[q*128 + tid] = g_W[b*2304 + q*128 + tid];
        if (tid < 3) sVV[tid] = g_V[b*4 + tid];
        __syncthreads();

        {
            #pragma unroll
            for (int pass = 0; pass < 2; pass++) {
                int p = pass*64 + (tid >> 1), half = tid & 1;
                if (p < m) {
                    const float4* src = (const float4*)(feats + (size_t)sPair[p]*80 + half*40);
                    float* dst = sF + p*FSTR + half*40;
                    #pragma unroll
                    for (int q = 0; q < 10; q++) {
                        float4 v = src[q];
                        dst[q*4+0]=v.x; dst[q*4+1]=v.y; dst[q*4+2]=v.z; dst[q*4+3]=v.w;
                    }
                }
            }
        }
        __syncthreads();

        int p = tid;
        if (p < m) {
            const float* f = sF + p*FSTR;
            float vv0 = sVV[0], vv1 = sVV[1], vv2 = sVV[2];

            float f1v[16];
            #pragma unroll
            for (int i = 0; i < 16; i++)
                f1v[i] = f[32+3*i]*vv0 + f[33+3*i]*vv1 + f[34+3*i]*vv2;

            float a0[32], hh[16];
            #pragma unroll
            for (int c = 0; c < 32; c++) a0[c] = 0.0f;
            #pragma unroll
            for (int k = 0; k < 16; k++) hh[k] = 0.0f;

            #pragma unroll 4
            for (int i = 0; i < 32; i++) {
                float fi = f[i];
                const float* w1r = sW + i*32;
                #pragma unroll
                for (int c = 0; c < 32; c++) a0[c] += fi * w1r[c];
                const float* w2r = sW + 1024 + i*16;
                #pragma unroll
                for (int k = 0; k < 16; k++) hh[k] += fi * w2r[k];
            }
            #pragma unroll 4
            for (int i = 0; i < 16; i++) {
                float fi = f1v[i];
                const float* w4r = sW + 1792 + i*32;
                #pragma unroll
                for (int c = 0; c < 32; c++) a0[c] += fi * w4r[c];
            }

            float* orow = g_partial + (size_t)sDst[p]*80;
            #pragma unroll
            for (int q = 0; q < 8; q++)
                ((float4*)orow)[q] = make_float4(a0[q*4], a0[q*4+1], a0[q*4+2], a0[q*4+3]);

            float o1[48];
            #pragma unroll
            for (int k = 0; k < 16; k++) {
                o1[3*k]   = vv0 * hh[k];
                o1[3*k+1] = vv1 * hh[k];
                o1[3*k+2] = vv2 * hh[k];
            }
            #pragma unroll 2
            for (int i = 0; i < 16; i++) {
                float fa = f[32+3*i], fb = f[33+3*i], fc = f[34+3*i];
                const float* w3r = sW + 1536 + i*16;
                #pragma unroll
                for (int k = 0; k < 16; k++) {
                    float w = w3r[k];
                    o1[3*k]   += fa * w;
                    o1[3*k+1] += fb * w;
                    o1[3*k+2] += fc * w;
                }
            }
            #pragma unroll
            for (int q = 0; q < 12; q++)
                ((float4*)(orow+32))[q] = make_float4(o1[q*4], o1[q*4+1], o1[q*4+2], o1[q*4+3]);
        }
        __syncthreads();
    }
}

// ------------- finalize: out[i] = sc(feats[i]) + sum of partials -------------
// partials for point i are CONTIGUOUS rows [i*MAXNB, i*MAXNB+cnt) -> sequential reads,
// summed in ascending r (fixed k_fill traversal order) -> deterministic.
__global__ void __launch_bounds__(512) k_final(const float* __restrict__ feats,
                                               const float* __restrict__ wsc0,
                                               const float* __restrict__ wsc1,
                                               float* __restrict__ out, int n)
{
    __shared__ float sW0[1024], sW1[256], sf[16][80];
    int tid = threadIdx.x;
    #pragma unroll
    for (int t = tid; t < 1024; t += 512) sW0[t] = wsc0[t] * 0.17677669529663687f; // /sqrt(32)
    if (tid < 256) sW1[tid] = wsc1[tid] * 0.25f;                                   // /sqrt(16)
    __syncthreads();

    int w = tid >> 5, lane = tid & 31;
    int i = blockIdx.x*16 + w;
    if (i >= n) return;

    const float* fr = feats + (size_t)i*80;
    sf[w][lane]      = fr[lane];
    sf[w][lane + 32] = fr[lane + 32];
    if (lane < 16) sf[w][lane + 64] = fr[lane + 64];
    __syncwarp();

    float a0 = 0.f, a1 = 0.f, a2 = 0.f;
    #pragma unroll
    for (int ii = 0; ii < 32; ii++) a0 += sf[w][ii] * sW0[ii*32 + lane];
    {
        int k = lane / 3, m = lane - 3*k;
        #pragma unroll
        for (int ii = 0; ii < 16; ii++) a1 += sf[w][32 + 3*ii + m] * sW1[ii*16 + k];
    }
    if (lane < 16) {
        int e = lane + 32; int k = e / 3, m = e - 3*k;
        #pragma unroll
        for (int ii = 0; ii < 16; ii++) a2 += sf[w][32 + 3*ii + m] * sW1[ii*16 + k];
    }

    int cnt = (int)g_pcnt[i];
    const float* base = g_partial + (size_t)i*MAXNB*80;
    for (int r = 0; r < cnt; r++) {
        const float* pp = base + r*80;
        a0 += pp[lane];
        a1 += pp[lane + 32];
        if (lane < 16) a2 += pp[lane + 64];
    }

    float* o = out + (size_t)i*80;
    o[lane] = a0; o[lane + 32] = a1;
    if (lane < 16) o[lane + 64] = a2;
}

// ------------------------------------ launch ------------------------------------
extern "C" void kernel_launch(void* const* d_in, const int* in_sizes, int n_in,
                              void* d_out, int out_size)
{
    const float* feats  = (const float*)d_in[0];
    const float* weight = (const float*)d_in[1];
    const float* w_sc0  = (const float*)d_in[2];
    const float* w_sc1  = (const float*)d_in[3];
    const int*   coords = (const int*)  d_in[4];
    int n = in_sizes[0] / 80;

    k_clear  <<<(BMW + 255)/256, 256>>>();
    k_buildW <<<NBINS, 256>>>(weight);

    int nb = (n + 255) / 256;
    k_scatter<<<nb, 256>>>(coords, n);
    k_fill   <<<nb, 256>>>(coords, n);

    k_gemm   <<<444, 128>>>(feats);
    k_final  <<<(n + 15)/16, 512>>>(feats, w_sc0, w_sc1, (float*)d_out, n);
}

// round 14
// speedup vs baseline: 1.6920x; 1.6920x over previous
#include <cuda_runtime.h>

#define GRIDN 192
#define VOLN (GRIDN*GRIDN*GRIDN)
#define BMW (GRIDN*GRIDN*6)
#define NBINS 80
#define NSUB 16
#define SUBCAP 512
#define NSB (NBINS*NSUB)              // 1280 sub-bins
#define PAIR_CAP (NSB*SUBCAP)
#define MAXN 200000
#define MAXNB 32
#define TILE 128
#define FSTR 81   // padded smem feature stride (odd -> conflict-free)

// ---------------- persistent device scratch ----------------
// g_vol needs NO per-launch clear: only read at cells whose g_bm bit is set,
// and bits are only set at cells k_scatter wrote in THIS launch.
__device__ int            g_vol[VOLN];
__device__ unsigned       g_bm[BMW];
__device__ float          g_W[NBINS*2304];             // factorized per-bin weights
__device__ float          g_V[NBINS*4];                // vv = sqrt(3)*unit(offset)
__device__ int            g_rowmask[25];
__device__ int            g_rowstart[25];
__device__ int            g_bdx[NBINS], g_bdy[NBINS], g_bdz[NBINS];
__device__ int            g_cursor[NSB];               // despread counters
__device__ int            g_pairnb[PAIR_CAP];          // source point index per pair
__device__ int            g_slots[MAXN*MAXNB];         // per-point pair slots (fixed order)
__device__ unsigned char  g_pcnt[MAXN];
__device__ float          g_partial[(size_t)PAIR_CAP*80];   // bin-contiguous partial rows

// ---------------- clear + geometry init fused (offsets with 1 <= d^2 <= 6) ----------
__global__ void k_clear()
{
    int i = blockIdx.x*blockDim.x + threadIdx.x;
    if (i < BMW)  g_bm[i] = 0u;
    if (i < NSB)  g_cursor[i] = 0;
    if (blockIdx.x == 0 && threadIdx.x == 0) {
        int bin = 0;
        for (int dx = -2; dx <= 2; dx++)
        for (int dy = -2; dy <= 2; dy++) {
            int row = (dx+2)*5 + (dy+2);
            int mask = 0;
            g_rowstart[row] = bin;
            for (int dz = -2; dz <= 2; dz++) {
                int d2 = dx*dx + dy*dy + dz*dz;
                if (d2 >= 1 && d2 <= 6) {
                    mask |= 1 << (dz+2);
                    g_bdx[bin] = dx; g_bdy[bin] = dy; g_bdz[bin] = dz;
                    float inv = 1.7320508075688772f / sqrtf((float)d2);
                    g_V[bin*4+0] = dx*inv; g_V[bin*4+1] = dy*inv; g_V[bin*4+2] = dz*inv;
                    bin++;
                }
            }
            g_rowmask[row] = mask;
        }
    }
}

__global__ void k_scatter(const int* __restrict__ coords, int n)
{
    int i = blockIdx.x*blockDim.x + threadIdx.x;
    if (i >= n) return;
    int x = coords[3*i+0], y = coords[3*i+1], z = coords[3*i+2];
    g_vol[(x*GRIDN + y)*GRIDN + z] = i;
    atomicOr(&g_bm[(x*GRIDN + y)*6 + (z >> 5)], 1u << (z & 31));
}

// ---------------- factorized per-bin weights: g_W[b] = scale * (EMB[b] @ weight)/125 ----
__global__ void __launch_bounds__(256) k_buildW(const float* __restrict__ weight)
{
    int b = blockIdx.x, tid = threadIdx.x;
    int dx = g_bdx[b], dy = g_bdy[b], dz = g_bdz[b];
    float d = sqrtf((float)(dx*dx + dy*dy + dz*dz));
    float e[8];
    const float h = 2.5f / 9.0f;
    const float C = 1.14136f * expf(2.0f);
    #pragma unroll
    for (int r = 0; r < 8; r++) {
        float t  = (d - h*(float)(r+1)) / h;
        float tt = t*t;
        e[r] = (tt < 1.0f) ? C * expf(-2.0f / (1.0f - tt)) : 0.0f;
    }
    const float A  = 0.14433756729740643f;   // 1/sqrt(48)
    const float A3 = 1.0f / 12.0f;           // A/sqrt(3)
    for (int j = tid; j < 2304; j += 256) {
        float w = 0.0f;
        #pragma unroll
        for (int r = 0; r < 8; r++) w += e[r] * __ldg(weight + r*2304 + j);
        float s = (j >= 1792) ? A3 : A;
        g_W[b*2304 + j] = s * w * (1.0f / 125.0f);
    }
}

// ---------------- occupancy probe: 5 z-bits around z for column (xx,yy) ----------------
__device__ __forceinline__ unsigned occ5(int xx, int yy, int z)
{
    int base = (xx*GRIDN + yy)*6;
    int zl = z - 2;
    int q  = zl >> 5;
    unsigned w0 = (q >= 0)   ? g_bm[base + q]     : 0u;
    unsigned w1 = (q + 1 < 6)? g_bm[base + q + 1] : 0u;
    unsigned v = __funnelshift_r(w0, w1, zl & 31) & 31u;
    if (zl + 4 > GRIDN - 1) v &= (31u >> (zl + 4 - (GRIDN - 1)));
    return v;
}

// discovery: phase 1 batches all 21 row probes (max MLP); phase 2 claims
// despread slots; slot ids recorded per-point in fixed traversal order
__global__ void k_fill(const int* __restrict__ coords, int n)
{
    int i = blockIdx.x*blockDim.x + threadIdx.x;
    if (i >= n) return;
    int x = __ldg(coords+3*i+0), y = __ldg(coords+3*i+1), z = __ldg(coords+3*i+2);
    int sub = i & (NSUB-1);

    unsigned am[25];
    #pragma unroll
    for (int row = 0; row < 25; row++) {
        int mask = g_rowmask[row];
        am[row] = 0u;
        if (!mask) continue;
        int dx = row/5 - 2, dy = row%5 - 2;
        int xx = x + dx, yy = y + dy;
        if (xx < 0 || xx >= GRIDN || yy < 0 || yy >= GRIDN) continue;
        am[row] = occ5(xx, yy, z) & (unsigned)mask;
    }

    int r = 0;
    #pragma unroll
    for (int row = 0; row < 25; row++) {
        unsigned a = am[row];
        if (!a) continue;
        int mask = g_rowmask[row];
        int dx = row/5 - 2, dy = row%5 - 2;
        int xx = x + dx, yy = y + dy;
        int rs = g_rowstart[row];
        while (a) {
            int bpos = __ffs(a) - 1; a &= a - 1;
            int bin = rs + __popc((unsigned)mask & ((1u << bpos) - 1u));
            int loc = atomicAdd(&g_cursor[bin*NSUB + sub], 1);
            if (loc < SUBCAP) {
                int slot = (bin*NSUB + sub)*SUBCAP + loc;
                int zz = z - 2 + bpos;
                g_pairnb[slot] = g_vol[(xx*GRIDN + yy)*GRIDN + zz];
                if (r < MAXNB) { g_slots[i*MAXNB + r] = slot; r++; }
            }
        }
    }
    g_pcnt[i] = (unsigned char)r;
}

// ---------------- factorized binned GEMM over 1280 sub-bins, 2 threads/pair ----------
// thread (p, h): computes out0 cols [h*16,h*16+16), hh[h*8..h*8+8), out1 elems [32+h*24, 32+h*24+24)
__global__ void __launch_bounds__(256) k_gemm(const float* __restrict__ feats)
{
    __shared__ float sF[TILE*FSTR];
    __shared__ float sW[2304];
    __shared__ float sVV[4];
    __shared__ int   sPair[TILE];
    __shared__ int   sCnt[NSB];
    __shared__ int   sTS[NSB+1];
    __shared__ int   sPart[257];
    int tid = threadIdx.x;

    #pragma unroll
    for (int q = 0; q < 5; q++) {
        int sb = tid*5 + q;
        sCnt[sb] = min(g_cursor[sb], SUBCAP);
    }
    __syncthreads();
    // two-level tile-count prefix scan
    {
        int loc = 0;
        #pragma unroll
        for (int q = 0; q < 5; q++) loc += (sCnt[tid*5 + q] + TILE - 1) / TILE;
        sPart[tid] = loc;
        __syncthreads();
        if (tid == 0) {
            int acc = 0;
            for (int j = 0; j < 256; j++) { int v = sPart[j]; sPart[j] = acc; acc += v; }
            sPart[256] = acc;
        }
        __syncthreads();
        int acc = sPart[tid];
        #pragma unroll
        for (int q = 0; q < 5; q++) {
            sTS[tid*5 + q] = acc;
            acc += (sCnt[tid*5 + q] + TILE - 1) / TILE;
        }
        if (tid == 0) sTS[NSB] = sPart[256];
        __syncthreads();
    }
    int ntiles = sTS[NSB];

    for (int t = blockIdx.x; t < ntiles; t += gridDim.x) {
        int lo = 0, hi = NSB;
        while (hi - lo > 1) { int mid = (lo + hi) >> 1; if (sTS[mid] <= t) lo = mid; else hi = mid; }
        int sb = lo;
        int b  = sb >> 4;
        int tloc  = t - sTS[sb];
        int pbase = sb*SUBCAP + tloc*TILE;
        int m = min(TILE, sCnt[sb] - tloc*TILE);

        if (tid < m) sPair[tid] = g_pairnb[pbase + tid];
        #pragma unroll
        for (int q = 0; q < 9; q++) sW[q*256 + tid] = g_W[b*2304 + q*256 + tid];
        if (tid < 3) sVV[tid] = g_V[b*4 + tid];
        __syncthreads();

        { // stage feature rows: 2 threads per row, single pass with 256 threads
            int p = tid >> 1, half = tid & 1;
            if (p < m) {
                const float4* src = (const float4*)(feats + (size_t)sPair[p]*80 + half*40);
                float* dst = sF + p*FSTR + half*40;
                #pragma unroll
                for (int q = 0; q < 10; q++) {
                    float4 v = src[q];
                    dst[q*4+0]=v.x; dst[q*4+1]=v.y; dst[q*4+2]=v.z; dst[q*4+3]=v.w;
                }
            }
        }
        __syncthreads();

        int p = tid >> 1, h = tid & 1;
        if (p < m) {
            const float* f = sF + p*FSTR;
            float vv0 = sVV[0], vv1 = sVV[1], vv2 = sVV[2];

            float f1v[16];
            #pragma unroll
            for (int i = 0; i < 16; i++)
                f1v[i] = f[32+3*i]*vv0 + f[33+3*i]*vv1 + f[34+3*i]*vv2;

            float a0[16], hh[8];
            #pragma unroll
            for (int c = 0; c < 16; c++) a0[c] = 0.0f;
            #pragma unroll
            for (int k = 0; k < 8; k++) hh[k] = 0.0f;

            const int c0 = h*16;     // out0 column base
            const int k0 = h*8;      // hh base

            #pragma unroll 4
            for (int i = 0; i < 32; i++) {
                float fi = f[i];
                const float* w1r = sW + i*32 + c0;
                #pragma unroll
                for (int c = 0; c < 16; c++) a0[c] += fi * w1r[c];
                const float* w2r = sW + 1024 + i*16 + k0;
                #pragma unroll
                for (int k = 0; k < 8; k++) hh[k] += fi * w2r[k];
            }
            #pragma unroll 4
            for (int i = 0; i < 16; i++) {
                float fi = f1v[i];
                const float* w4r = sW + 1792 + i*32 + c0;
                #pragma unroll
                for (int c = 0; c < 16; c++) a0[c] += fi * w4r[c];
            }

            float* orow = g_partial + (size_t)(pbase + p)*80;
            #pragma unroll
            for (int q = 0; q < 4; q++)
                ((float4*)(orow + c0))[q] = make_float4(a0[q*4], a0[q*4+1], a0[q*4+2], a0[q*4+3]);

            float o1[24];
            #pragma unroll
            for (int k = 0; k < 8; k++) {
                o1[3*k]   = vv0 * hh[k];
                o1[3*k+1] = vv1 * hh[k];
                o1[3*k+2] = vv2 * hh[k];
            }
            #pragma unroll 2
            for (int i = 0; i < 16; i++) {
                float fa = f[32+3*i], fb = f[33+3*i], fc = f[34+3*i];
                const float* w3r = sW + 1536 + i*16 + k0;
                #pragma unroll
                for (int k = 0; k < 8; k++) {
                    float w = w3r[k];
                    o1[3*k]   += fa * w;
                    o1[3*k+1] += fb * w;
                    o1[3*k+2] += fc * w;
                }
            }
            // out1 elems [32 + h*24, 32 + h*24 + 24): byte offsets 128+96h, 16B aligned
            #pragma unroll
            for (int q = 0; q < 6; q++)
                ((float4*)(orow + 32 + h*24))[q] = make_float4(o1[q*4], o1[q*4+1], o1[q*4+2], o1[q*4+3]);
        }
        __syncthreads();
    }
}

// ------------- finalize: out[i] = sc(feats[i]) + sum of partials (fixed order) -------------
__global__ void __launch_bounds__(512) k_final(const float* __restrict__ feats,
                                               const float* __restrict__ wsc0,
                                               const float* __restrict__ wsc1,
                                               float* __restrict__ out, int n)
{
    __shared__ float sW0[1024], sW1[256], sf[16][80];
    int tid = threadIdx.x;
    #pragma unroll
    for (int t = tid; t < 1024; t += 512) sW0[t] = wsc0[t] * 0.17677669529663687f; // /sqrt(32)
    if (tid < 256) sW1[tid] = wsc1[tid] * 0.25f;                                   // /sqrt(16)
    __syncthreads();

    int w = tid >> 5, lane = tid & 31;
    int i = blockIdx.x*16 + w;
    if (i >= n) return;

    const float* fr = feats + (size_t)i*80;
    sf[w][lane]      = fr[lane];
    sf[w][lane + 32] = fr[lane + 32];
    if (lane < 16) sf[w][lane + 64] = fr[lane + 64];
    __syncwarp();

    float a0 = 0.f, a1 = 0.f, a2 = 0.f;
    #pragma unroll
    for (int ii = 0; ii < 32; ii++) a0 += sf[w][ii] * sW0[ii*32 + lane];
    {
        int k = lane / 3, m = lane - 3*k;
        #pragma unroll
        for (int ii = 0; ii < 16; ii++) a1 += sf[w][32 + 3*ii + m] * sW1[ii*16 + k];
    }
    if (lane < 16) {
        int e = lane + 32; int k = e / 3, m = e - 3*k;
        #pragma unroll
        for (int ii = 0; ii < 16; ii++) a2 += sf[w][32 + 3*ii + m] * sW1[ii*16 + k];
    }

    int cnt = (int)g_pcnt[i];
    const int* sl = g_slots + i*MAXNB;
    for (int r = 0; r < cnt; r++) {
        const float* pp = g_partial + (size_t)sl[r]*80;
        a0 += pp[lane];
        a1 += pp[lane + 32];
        if (lane < 16) a2 += pp[lane + 64];
    }

    float* o = out + (size_t)i*80;
    o[lane] = a0; o[lane + 32] = a1;
    if (lane < 16) o[lane + 64] = a2;
}

// ------------------------------------ launch ------------------------------------
extern "C" void kernel_launch(void* const* d_in, const int* in_sizes, int n_in,
                              void* d_out, int out_size)
{
    const float* feats  = (const float*)d_in[0];
    const float* weight = (const float*)d_in[1];
    const float* w_sc0  = (const float*)d_in[2];
    const float* w_sc1  = (const float*)d_in[3];
    const int*   coords = (const int*)  d_in[4];
    int n = in_sizes[0] / 80;

    k_clear  <<<(BMW + 255)/256, 256>>>();
    k_buildW <<<NBINS, 256>>>(weight);

    int nb = (n + 255) / 256;
    k_scatter<<<nb, 256>>>(coords, n);
    k_fill   <<<nb, 256>>>(coords, n);

    k_gemm   <<<444, 256>>>(feats);
    k_final  <<<(n + 15)/16, 512>>>(feats, w_sc0, w_sc1, (float*)d_out, n);
}